// round 7
// baseline (speedup 1.0000x reference)
#include <cuda_runtime.h>
#include <cuda_bf16.h>
#include <math.h>

#define BATCH 2
#define NPTS  8192
#define CH    128
#define KNN   8
#define MTOT  (BATCH * NPTS)

// ---------------- scratch (no allocations allowed) ----------------
__device__ float g_q[MTOT * CH];
__device__ float g_k[MTOT * CH];
__device__ float g_v[MTOT * CH];
__device__ int   g_idx[MTOT * KNN];
__device__ uint4 g_agg2[MTOT * 64];    // agg split, X-pattern (hi,lo,hi,lo)

// ---------------- fp32 -> (hi,lo) bf16 split helpers ----------------
__device__ __forceinline__ void split_bf16(float x, unsigned short& h, unsigned short& l) {
    __nv_bfloat16 hb = __float2bfloat16(x);
    float hf = __bfloat162float(hb);
    __nv_bfloat16 lb = __float2bfloat16(x - hf);
    h = __bfloat16_as_ushort(hb);
    l = __bfloat16_as_ushort(lb);
}
__device__ __forceinline__ unsigned pack_hilo(float x) {   // X-pattern word (hi,lo)
    unsigned short h, l; split_bf16(x, h, l);
    return ((unsigned)l << 16) | (unsigned)h;
}
__device__ __forceinline__ void pack_w(float x, unsigned& p0, unsigned& p1) { // (hi,hi),(lo,lo)
    unsigned short h, l; split_bf16(x, h, l);
    p0 = ((unsigned)h << 16) | h;
    p1 = ((unsigned)l << 16) | l;
}

// ---------------- tensor-core GEMM:  Y = X @ W^T via bf16 split-K ----------------
// W fp32, split inline. X either fp32 (SPLIT_X) or pre-split uint4 X-pattern.
// CTA = 128x128, 256 threads = 8 warps (4x2), warp tile 32x64, mma.m16n8k16.
// smem rows padded to 144B -> conflict-free LDS.32 fragment loads.
template <bool SPLIT_X>
__device__ __forceinline__ void mma_gemm_tile(const void* __restrict__ Xv,
                                              const float* __restrict__ Wf,
                                              float* __restrict__ Y, int m0,
                                              char* smem)
{
    unsigned char* xs = (unsigned char*)smem;
    unsigned char* ws = (unsigned char*)smem + 128 * 144;
    const int tid  = threadIdx.x;
    const int lane = tid & 31;
    const int warp = tid >> 5;
    const int wm   = warp >> 1;
    const int wn   = warp & 1;
    const int g    = lane >> 2;
    const int c4   = lane & 3;

    float acc[2][8][4];
#pragma unroll
    for (int i = 0; i < 2; i++)
#pragma unroll
        for (int t = 0; t < 8; t++)
#pragma unroll
            for (int r = 0; r < 4; r++) acc[i][t][r] = 0.f;

    for (int kc = 0; kc < 8; kc++) {        // K' = 512 in chunks of 64
        __syncthreads();
#pragma unroll
        for (int i = 0; i < 4; i++) {
            int s  = tid + i * 256;         // 0..1023
            int r  = s >> 3;                // row 0..127
            int f4 = s & 7;                 // 16B unit 0..7
            if (SPLIT_X) {
                const float* X = (const float*)Xv;
                float2 xv = *(const float2*)(X + (size_t)(m0 + r) * CH + kc * 16 + f4 * 2);
                unsigned p0 = pack_hilo(xv.x), p1 = pack_hilo(xv.y);
                *(uint4*)(xs + r * 144 + f4 * 16) = make_uint4(p0, p0, p1, p1);
            } else {
                const uint4* X2 = (const uint4*)Xv;
                *(uint4*)(xs + r * 144 + f4 * 16) = X2[(size_t)(m0 + r) * 64 + kc * 8 + f4];
            }
            float2 wv = *(const float2*)(Wf + (size_t)r * CH + kc * 16 + f4 * 2);
            unsigned a0, a1, b0, b1;
            pack_w(wv.x, a0, a1);
            pack_w(wv.y, b0, b1);
            *(uint4*)(ws + r * 144 + f4 * 16) = make_uint4(a0, a1, b0, b1);
        }
        __syncthreads();
#pragma unroll
        for (int ks = 0; ks < 4; ks++) {    // 4 x k16 steps
            unsigned a[2][4], b[8][2];
#pragma unroll
            for (int i = 0; i < 2; i++)
#pragma unroll
                for (int j = 0; j < 4; j++) {
                    int row = wm * 32 + i * 16 + g + 8 * (j & 1);
                    int off = ks * 32 + (j >> 1) * 16 + c4 * 4;
                    a[i][j] = *(const unsigned*)(xs + row * 144 + off);
                }
#pragma unroll
            for (int t = 0; t < 8; t++)
#pragma unroll
                for (int r = 0; r < 2; r++) {
                    int n   = wn * 64 + t * 8 + g;
                    int off = ks * 32 + r * 16 + c4 * 4;
                    b[t][r] = *(const unsigned*)(ws + n * 144 + off);
                }
#pragma unroll
            for (int i = 0; i < 2; i++)
#pragma unroll
                for (int t = 0; t < 8; t++)
                    asm volatile(
                        "mma.sync.aligned.m16n8k16.row.col.f32.bf16.bf16.f32 "
                        "{%0,%1,%2,%3}, {%4,%5,%6,%7}, {%8,%9}, {%0,%1,%2,%3};"
                        : "+f"(acc[i][t][0]), "+f"(acc[i][t][1]),
                          "+f"(acc[i][t][2]), "+f"(acc[i][t][3])
                        : "r"(a[i][0]), "r"(a[i][1]), "r"(a[i][2]), "r"(a[i][3]),
                          "r"(b[t][0]), "r"(b[t][1]));
        }
    }
#pragma unroll
    for (int i = 0; i < 2; i++)
#pragma unroll
        for (int t = 0; t < 8; t++) {
            int row = m0 + wm * 32 + i * 16 + g;
            int col = wn * 64 + t * 8 + 2 * c4;
            *(float2*)(Y + (size_t)row * CH + col)       = make_float2(acc[i][t][0], acc[i][t][1]);
            *(float2*)(Y + (size_t)(row + 8) * CH + col) = make_float2(acc[i][t][2], acc[i][t][3]);
        }
}

__global__ __launch_bounds__(256) void qkv_mma_kernel(const float* __restrict__ feats,
                                                      const float* __restrict__ Wq,
                                                      const float* __restrict__ Wk,
                                                      const float* __restrict__ Wv)
{
    __shared__ __align__(16) char smem[2 * 128 * 144];
    int w = blockIdx.y;
    const float* W = (w == 0) ? Wq : (w == 1) ? Wk : Wv;
    float* Y = (w == 0) ? g_q : (w == 1) ? g_k : g_v;
    mma_gemm_tile<true>(feats, W, Y, blockIdx.x * 128, smem);
}

__global__ __launch_bounds__(256) void out_mma_kernel(const float* __restrict__ Wo,
                                                      float* __restrict__ out)
{
    __shared__ __align__(16) char smem[2 * 128 * 144];
    mma_gemm_tile<false>(g_agg2, Wo, out, blockIdx.x * 128, smem);
}

// ---------------- KNN: warp top-8 with deferred-sort candidate buffer ----------
// e-space ordering: e = csq - 2*dot (query-constant shift of d2).
// Fast path: 4 candidates/lane, 3 FMA each, one __any ballot per 128 cands.
// Qualifying lane-minima are compacted (ballot + __fns + shfl) into a 32-slot
// warp register buffer; a flush (32-lane bitonic sort + <=8 early-exit inserts)
// happens only when the buffer fills or the scan ends.
#define QW  4
#define CCH 2048

__device__ __forceinline__ void knn_flush(float& val, int& idx, float& thr,
                                          float& bufv, int& bufi, int& cnt)
{
    const unsigned full = 0xffffffffu;
    const int lane = threadIdx.x & 31;
    float v = bufv; int bi = bufi;
#pragma unroll
    for (int k = 2; k <= 32; k <<= 1) {
#pragma unroll
        for (int jj = k >> 1; jj > 0; jj >>= 1) {
            float ov = __shfl_xor_sync(full, v, jj);
            int   oi = __shfl_xor_sync(full, bi, jj);
            bool up   = ((lane & k) == 0);
            bool lowr = ((lane & jj) == 0);
            bool take = (lowr == up) ? (ov < v) : (ov > v);
            if (take) { v = ov; bi = oi; }
        }
    }
    for (int r = 0; r < 8; r++) {             // sorted ascending: early exit ok
        float dv = __shfl_sync(full, v, r);
        if (dv >= thr) break;                 // warp-uniform
        int di = __shfl_sync(full, bi, r);
        float pv = __shfl_up_sync(full, val, 1);
        int   pi = __shfl_up_sync(full, idx, 1);
        unsigned le = __ballot_sync(full, val <= dv);
        int pos = __popc(le & 0xff);
        if (lane == pos)                 { val = dv; idx = di; }
        else if (lane > pos && lane < 8) { val = pv; idx = pi; }
        thr = __shfl_sync(full, val, 7);
    }
    cnt = 0; bufv = 3.0e38f;
}

__global__ __launch_bounds__(256, 3) void knn_kernel(const float* __restrict__ coords,
                                                     int* __restrict__ out_idx)
{
    __shared__ float sx[CCH], sy[CCH], sz[CCH], ss[CCH];
    const unsigned full = 0xffffffffu;
    const int b     = blockIdx.y;
    const int warp  = threadIdx.x >> 5;
    const int lane  = threadIdx.x & 31;
    const int qbase = blockIdx.x * (8 * QW) + warp * QW;
    const float* cb = coords + (size_t)b * NPTS * 3;

    float m2x[QW], m2y[QW], m2z[QW];
#pragma unroll
    for (int u = 0; u < QW; u++) {
        m2x[u] = -2.f * cb[(qbase + u) * 3 + 0];
        m2y[u] = -2.f * cb[(qbase + u) * 3 + 1];
        m2z[u] = -2.f * cb[(qbase + u) * 3 + 2];
    }

    float val[QW], thr[QW], bufv[QW];
    int idx[QW], bufi[QW], cnt[QW];
#pragma unroll
    for (int u = 0; u < QW; u++) {
        val[u] = 3.0e38f; thr[u] = 3.0e38f; bufv[u] = 3.0e38f;
        idx[u] = -1; bufi[u] = -1; cnt[u] = 0;
    }

    for (int c0 = 0; c0 < NPTS; c0 += CCH) {
        __syncthreads();
        for (int t = threadIdx.x; t < CCH; t += 256) {
            float x = cb[(c0 + t) * 3 + 0];
            float y = cb[(c0 + t) * 3 + 1];
            float z = cb[(c0 + t) * 3 + 2];
            sx[t] = x; sy[t] = y; sz[t] = z;
            ss[t] = fmaf(z, z, fmaf(y, y, x * x));
        }
        __syncthreads();

        for (int j0 = 0; j0 < CCH; j0 += 128) {
            int base = j0 + lane * 4;
            float4 cx = *(const float4*)&sx[base];
            float4 cy = *(const float4*)&sy[base];
            float4 cz = *(const float4*)&sz[base];
            float4 cs = *(const float4*)&ss[base];
            int jb = c0 + j0;                        // warp-uniform
#pragma unroll
            for (int u = 0; u < QW; u++) {
                float e0 = fmaf(m2z[u], cz.x, fmaf(m2y[u], cy.x, fmaf(m2x[u], cx.x, cs.x)));
                float e1 = fmaf(m2z[u], cz.y, fmaf(m2y[u], cy.y, fmaf(m2x[u], cx.y, cs.y)));
                float e2 = fmaf(m2z[u], cz.z, fmaf(m2y[u], cy.z, fmaf(m2x[u], cx.z, cs.z)));
                float e3 = fmaf(m2z[u], cz.w, fmaf(m2y[u], cy.w, fmaf(m2x[u], cx.w, cs.w)));
                float lm = fminf(fminf(e0, e1), fminf(e2, e3));
                if (!__any_sync(full, lm < thr[u])) continue;

                // slow path: compact qualifying lane-minima into the buffer
                float ev0 = e0, ev1 = e1, ev2 = e2, ev3 = e3;
                for (;;) {
                    float lm2 = ev0; int li = 0;
                    if (ev1 < lm2) { lm2 = ev1; li = 1; }
                    if (ev2 < lm2) { lm2 = ev2; li = 2; }
                    if (ev3 < lm2) { lm2 = ev3; li = 3; }
                    unsigned mb = __ballot_sync(full, lm2 < thr[u]);
                    if (!mb) break;
                    int npush = __popc(mb);
                    if (cnt[u] + npush > 32) {
                        knn_flush(val[u], idx[u], thr[u], bufv[u], bufi[u], cnt[u]);
                        continue;                    // re-ballot vs tightened thr
                    }
                    int ofs = lane - cnt[u] + 1;
                    int src = __fns(mb, 0, ofs > 0 ? ofs : 1) & 31;
                    float pv = __shfl_sync(full, lm2, src);
                    int   pl = __shfl_sync(full, li, src);
                    if (lane >= cnt[u] && lane < cnt[u] + npush) {
                        bufv[u] = pv;
                        bufi[u] = jb + (src << 2) + pl;
                    }
                    cnt[u] += npush;
                    if ((mb >> lane) & 1) {          // consume pushed minimum
                        if (li == 0) ev0 = 3.0e38f;
                        else if (li == 1) ev1 = 3.0e38f;
                        else if (li == 2) ev2 = 3.0e38f;
                        else ev3 = 3.0e38f;
                    }
                }
            }
        }
    }

#pragma unroll
    for (int u = 0; u < QW; u++)
        if (cnt[u] > 0)
            knn_flush(val[u], idx[u], thr[u], bufv[u], bufi[u], cnt[u]);

    if (lane < KNN) {
#pragma unroll
        for (int u = 0; u < QW; u++)
            out_idx[((size_t)b * NPTS + qbase + u) * KNN + lane] = idx[u];
    }
}

// ---------------- attention over K=8 neighbors (float4, writes bf16 hi/lo agg) ---
__global__ __launch_bounds__(256) void attn_kernel(const float* __restrict__ coords,
                                                   const float* __restrict__ logg)
{
    const int gq   = blockIdx.x * 8 + (threadIdx.x >> 5);
    const int b    = gq >> 13;
    const int q    = gq & (NPTS - 1);
    const int lane = threadIdx.x & 31;
    const float lg = *logg;
    const float inv_sqrt_c = 0.08838834764831845f;   // 1/sqrt(128)

    float4 qv = *(const float4*)(g_q + (size_t)gq * CH + lane * 4);

    const float* cb = coords + (size_t)b * NPTS * 3;
    const float qx = cb[q * 3 + 0], qy = cb[q * 3 + 1], qz = cb[q * 3 + 2];

    int nb[KNN];
#pragma unroll
    for (int t = 0; t < KNN; t++) nb[t] = g_idx[(size_t)gq * KNN + t];

    float sc[KNN];
#pragma unroll
    for (int t = 0; t < KNN; t++) {
        float4 kv = *(const float4*)(g_k + ((size_t)b * NPTS + nb[t]) * CH + lane * 4);
        float d = qv.x * kv.x;
        d = fmaf(qv.y, kv.y, d);
        d = fmaf(qv.z, kv.z, d);
        d = fmaf(qv.w, kv.w, d);
#pragma unroll
        for (int off = 16; off; off >>= 1) d += __shfl_xor_sync(0xffffffffu, d, off);
        float dx = qx - cb[nb[t] * 3 + 0];
        float dy = qy - cb[nb[t] * 3 + 1];
        float dz = qz - cb[nb[t] * 3 + 2];
        float d2 = fmaf(dz, dz, fmaf(dy, dy, dx * dx));
        float dist = (d2 > 0.f) ? sqrtf(d2) : 0.f;     // _safe_norm
        float gw = expf(lg * dist);
        sc[t] = d * inv_sqrt_c * gw;
    }
    float m = sc[0];
#pragma unroll
    for (int t = 1; t < KNN; t++) m = fmaxf(m, sc[t]);
    float ssum = 0.f;
#pragma unroll
    for (int t = 0; t < KNN; t++) { sc[t] = expf(sc[t] - m); ssum += sc[t]; }
    float inv = 1.f / ssum;

    float4 acc = make_float4(0.f, 0.f, 0.f, 0.f);
#pragma unroll
    for (int t = 0; t < KNN; t++) {
        float4 vv = *(const float4*)(g_v + ((size_t)b * NPTS + nb[t]) * CH + lane * 4);
        float wt = sc[t] * inv;
        acc.x = fmaf(wt, vv.x, acc.x);
        acc.y = fmaf(wt, vv.y, acc.y);
        acc.z = fmaf(wt, vv.z, acc.z);
        acc.w = fmaf(wt, vv.w, acc.w);
    }
    // write agg in bf16 hi/lo X-pattern: channels (4l,4l+1) and (4l+2,4l+3)
    unsigned pa = pack_hilo(acc.x), pb = pack_hilo(acc.y);
    unsigned pc = pack_hilo(acc.z), pd = pack_hilo(acc.w);
    g_agg2[(size_t)gq * 64 + lane * 2 + 0] = make_uint4(pa, pa, pb, pb);
    g_agg2[(size_t)gq * 64 + lane * 2 + 1] = make_uint4(pc, pc, pd, pd);
}

// ---------------- launch ----------------
extern "C" void kernel_launch(void* const* d_in, const int* in_sizes, int n_in,
                              void* d_out, int out_size)
{
    const float* feats  = (const float*)d_in[0];
    const float* coords = (const float*)d_in[1];
    const float* Wq     = (const float*)d_in[2];
    const float* Wk     = (const float*)d_in[3];
    const float* Wv     = (const float*)d_in[4];
    const float* Wo     = (const float*)d_in[5];
    const float* logg   = (const float*)d_in[6];
    float* out = (float*)d_out;

    int* idx_ptr = nullptr;
    cudaGetSymbolAddress((void**)&idx_ptr, g_idx);

    // KNN top-8 per query (32 queries/CTA)
    knn_kernel<<<dim3(NPTS / 32, BATCH), 256>>>(coords, idx_ptr);

    // q,k,v projections on tensor cores (feats + W split inline)
    qkv_mma_kernel<<<dim3(MTOT / 128, 3), 256>>>(feats, Wq, Wk, Wv);

    // neighbor attention -> g_agg2 (bf16 hi/lo)
    attn_kernel<<<MTOT / 8, 256>>>(coords, logg);

    // output projection (Wo split inline)
    out_mma_kernel<<<MTOT / 128, 256>>>(Wo, out);
}

// round 8
// speedup vs baseline: 1.4783x; 1.4783x over previous
#include <cuda_runtime.h>
#include <cuda_bf16.h>
#include <math.h>

#define BATCH 2
#define NPTS  8192
#define CH    128
#define KNN   8
#define MTOT  (BATCH * NPTS)

// ---------------- scratch (no allocations allowed) ----------------
__device__ float g_q[MTOT * CH];
__device__ float g_k[MTOT * CH];
__device__ float g_v[MTOT * CH];
__device__ int   g_idx[MTOT * KNN];
__device__ uint4 g_agg2[MTOT * 64];    // agg split, X-pattern (hi,lo,hi,lo)

// ---------------- fp32 -> (hi,lo) bf16 split helpers ----------------
__device__ __forceinline__ void split_bf16(float x, unsigned short& h, unsigned short& l) {
    __nv_bfloat16 hb = __float2bfloat16(x);
    float hf = __bfloat162float(hb);
    __nv_bfloat16 lb = __float2bfloat16(x - hf);
    h = __bfloat16_as_ushort(hb);
    l = __bfloat16_as_ushort(lb);
}
__device__ __forceinline__ unsigned pack_hilo(float x) {   // X-pattern word (hi,lo)
    unsigned short h, l; split_bf16(x, h, l);
    return ((unsigned)l << 16) | (unsigned)h;
}
__device__ __forceinline__ void pack_w(float x, unsigned& p0, unsigned& p1) { // (hi,hi),(lo,lo)
    unsigned short h, l; split_bf16(x, h, l);
    p0 = ((unsigned)h << 16) | h;
    p1 = ((unsigned)l << 16) | l;
}

// ---------------- tensor-core GEMM:  Y = X @ W^T via bf16 split-K ----------------
// W fp32, split inline. X either fp32 (SPLIT_X) or pre-split uint4 X-pattern.
// CTA = 128x128, 256 threads = 8 warps (4x2), warp tile 32x64, mma.m16n8k16.
// smem rows padded to 144B -> conflict-free LDS.32 fragment loads.
template <bool SPLIT_X>
__device__ __forceinline__ void mma_gemm_tile(const void* __restrict__ Xv,
                                              const float* __restrict__ Wf,
                                              float* __restrict__ Y, int m0,
                                              char* smem)
{
    unsigned char* xs = (unsigned char*)smem;
    unsigned char* ws = (unsigned char*)smem + 128 * 144;
    const int tid  = threadIdx.x;
    const int lane = tid & 31;
    const int warp = tid >> 5;
    const int wm   = warp >> 1;
    const int wn   = warp & 1;
    const int g    = lane >> 2;
    const int c4   = lane & 3;

    float acc[2][8][4];
#pragma unroll
    for (int i = 0; i < 2; i++)
#pragma unroll
        for (int t = 0; t < 8; t++)
#pragma unroll
            for (int r = 0; r < 4; r++) acc[i][t][r] = 0.f;

    for (int kc = 0; kc < 8; kc++) {        // K' = 512 in chunks of 64
        __syncthreads();
#pragma unroll
        for (int i = 0; i < 4; i++) {
            int s  = tid + i * 256;         // 0..1023
            int r  = s >> 3;                // row 0..127
            int f4 = s & 7;                 // 16B unit 0..7
            if (SPLIT_X) {
                const float* X = (const float*)Xv;
                float2 xv = *(const float2*)(X + (size_t)(m0 + r) * CH + kc * 16 + f4 * 2);
                unsigned p0 = pack_hilo(xv.x), p1 = pack_hilo(xv.y);
                *(uint4*)(xs + r * 144 + f4 * 16) = make_uint4(p0, p0, p1, p1);
            } else {
                const uint4* X2 = (const uint4*)Xv;
                *(uint4*)(xs + r * 144 + f4 * 16) = X2[(size_t)(m0 + r) * 64 + kc * 8 + f4];
            }
            float2 wv = *(const float2*)(Wf + (size_t)r * CH + kc * 16 + f4 * 2);
            unsigned a0, a1, b0, b1;
            pack_w(wv.x, a0, a1);
            pack_w(wv.y, b0, b1);
            *(uint4*)(ws + r * 144 + f4 * 16) = make_uint4(a0, a1, b0, b1);
        }
        __syncthreads();
#pragma unroll
        for (int ks = 0; ks < 4; ks++) {    // 4 x k16 steps
            unsigned a[2][4], b[8][2];
#pragma unroll
            for (int i = 0; i < 2; i++)
#pragma unroll
                for (int j = 0; j < 4; j++) {
                    int row = wm * 32 + i * 16 + g + 8 * (j & 1);
                    int off = ks * 32 + (j >> 1) * 16 + c4 * 4;
                    a[i][j] = *(const unsigned*)(xs + row * 144 + off);
                }
#pragma unroll
            for (int t = 0; t < 8; t++)
#pragma unroll
                for (int r = 0; r < 2; r++) {
                    int n   = wn * 64 + t * 8 + g;
                    int off = ks * 32 + r * 16 + c4 * 4;
                    b[t][r] = *(const unsigned*)(ws + n * 144 + off);
                }
#pragma unroll
            for (int i = 0; i < 2; i++)
#pragma unroll
                for (int t = 0; t < 8; t++)
                    asm volatile(
                        "mma.sync.aligned.m16n8k16.row.col.f32.bf16.bf16.f32 "
                        "{%0,%1,%2,%3}, {%4,%5,%6,%7}, {%8,%9}, {%0,%1,%2,%3};"
                        : "+f"(acc[i][t][0]), "+f"(acc[i][t][1]),
                          "+f"(acc[i][t][2]), "+f"(acc[i][t][3])
                        : "r"(a[i][0]), "r"(a[i][1]), "r"(a[i][2]), "r"(a[i][3]),
                          "r"(b[t][0]), "r"(b[t][1]));
        }
    }
#pragma unroll
    for (int i = 0; i < 2; i++)
#pragma unroll
        for (int t = 0; t < 8; t++) {
            int row = m0 + wm * 32 + i * 16 + g;
            int col = wn * 64 + t * 8 + 2 * c4;
            *(float2*)(Y + (size_t)row * CH + col)       = make_float2(acc[i][t][0], acc[i][t][1]);
            *(float2*)(Y + (size_t)(row + 8) * CH + col) = make_float2(acc[i][t][2], acc[i][t][3]);
        }
}

__global__ __launch_bounds__(256) void qkv_mma_kernel(const float* __restrict__ feats,
                                                      const float* __restrict__ Wq,
                                                      const float* __restrict__ Wk,
                                                      const float* __restrict__ Wv)
{
    __shared__ __align__(16) char smem[2 * 128 * 144];
    int w = blockIdx.y;
    const float* W = (w == 0) ? Wq : (w == 1) ? Wk : Wv;
    float* Y = (w == 0) ? g_q : (w == 1) ? g_k : g_v;
    mma_gemm_tile<true>(feats, W, Y, blockIdx.x * 128, smem);
}

__global__ __launch_bounds__(256) void out_mma_kernel(const float* __restrict__ Wo,
                                                      float* __restrict__ out)
{
    __shared__ __align__(16) char smem[2 * 128 * 144];
    mma_gemm_tile<false>(g_agg2, Wo, out, blockIdx.x * 128, smem);
}

// ---------------- KNN: warp top-8, pop-global-min slow path ----------------
// e-space ordering: e = csq - 2*dot (query-constant shift of d2; same top-k set).
// Fast path: 4 candidates/lane (float4 LDS), 3 FMA each, one __any per
// 128-candidate group per query. On fire: repeatedly pop the warp-global
// minimum (fmin butterfly) and insert it into the distributed sorted top-8
// (lane j<8 owns slot j). Rounds per fire = exact inserts + 1.
#define QW  4
#define CCH 2048

__global__ __launch_bounds__(256, 3) void knn_kernel(const float* __restrict__ coords,
                                                     int* __restrict__ out_idx)
{
    __shared__ float sx[CCH], sy[CCH], sz[CCH], ss[CCH];
    const unsigned full = 0xffffffffu;
    const int b     = blockIdx.y;
    const int warp  = threadIdx.x >> 5;
    const int lane  = threadIdx.x & 31;
    const int qbase = blockIdx.x * (8 * QW) + warp * QW;
    const float* cb = coords + (size_t)b * NPTS * 3;

    float m2x[QW], m2y[QW], m2z[QW];
#pragma unroll
    for (int u = 0; u < QW; u++) {
        m2x[u] = -2.f * cb[(qbase + u) * 3 + 0];
        m2y[u] = -2.f * cb[(qbase + u) * 3 + 1];
        m2z[u] = -2.f * cb[(qbase + u) * 3 + 2];
    }

    float val[QW], thr[QW];
    int idx[QW];
#pragma unroll
    for (int u = 0; u < QW; u++) { val[u] = 3.0e38f; thr[u] = 3.0e38f; idx[u] = -1; }

    for (int c0 = 0; c0 < NPTS; c0 += CCH) {
        __syncthreads();
        for (int t = threadIdx.x; t < CCH; t += 256) {
            float x = cb[(c0 + t) * 3 + 0];
            float y = cb[(c0 + t) * 3 + 1];
            float z = cb[(c0 + t) * 3 + 2];
            sx[t] = x; sy[t] = y; sz[t] = z;
            ss[t] = fmaf(z, z, fmaf(y, y, x * x));
        }
        __syncthreads();

        for (int j0 = 0; j0 < CCH; j0 += 128) {
            int base = j0 + lane * 4;
            float4 cx = *(const float4*)&sx[base];
            float4 cy = *(const float4*)&sy[base];
            float4 cz = *(const float4*)&sz[base];
            float4 cs = *(const float4*)&ss[base];
            int jb = c0 + j0;                        // warp-uniform
#pragma unroll
            for (int u = 0; u < QW; u++) {
                float e0 = fmaf(m2z[u], cz.x, fmaf(m2y[u], cy.x, fmaf(m2x[u], cx.x, cs.x)));
                float e1 = fmaf(m2z[u], cz.y, fmaf(m2y[u], cy.y, fmaf(m2x[u], cx.y, cs.y)));
                float e2 = fmaf(m2z[u], cz.z, fmaf(m2y[u], cy.z, fmaf(m2x[u], cx.z, cs.z)));
                float e3 = fmaf(m2z[u], cz.w, fmaf(m2y[u], cy.w, fmaf(m2x[u], cx.w, cs.w)));
                float lm = fminf(fminf(e0, e1), fminf(e2, e3));
                if (!__any_sync(full, lm < thr[u])) continue;

                // slow path: pop warp-global minimum repeatedly
                float ev0 = e0, ev1 = e1, ev2 = e2, ev3 = e3;
                for (;;) {
                    float lmin = ev0; int li = 0;
                    if (ev1 < lmin) { lmin = ev1; li = 1; }
                    if (ev2 < lmin) { lmin = ev2; li = 2; }
                    if (ev3 < lmin) { lmin = ev3; li = 3; }
                    float bv = lmin;
#pragma unroll
                    for (int off = 16; off; off >>= 1)
                        bv = fminf(bv, __shfl_xor_sync(full, bv, off));
                    if (bv >= thr[u]) break;          // warp-uniform
                    unsigned who = __ballot_sync(full, lmin == bv);
                    int src = __ffs(who) - 1;
                    int sl  = __shfl_sync(full, li, src);
                    int in  = jb + (src << 2) + sl;
                    // insert bv into distributed sorted top-8
                    float pv = __shfl_up_sync(full, val[u], 1);
                    int   pi = __shfl_up_sync(full, idx[u], 1);
                    unsigned le = __ballot_sync(full, val[u] <= bv);
                    int pos = __popc(le & 0xff);
                    if (lane == pos)                 { val[u] = bv; idx[u] = in; }
                    else if (lane > pos && lane < 8) { val[u] = pv; idx[u] = pi; }
                    thr[u] = __shfl_sync(full, val[u], 7);
                    // consume popped slot on the owner lane
                    if (lane == src) {
                        if (li == 0) ev0 = 3.0e38f;
                        else if (li == 1) ev1 = 3.0e38f;
                        else if (li == 2) ev2 = 3.0e38f;
                        else ev3 = 3.0e38f;
                    }
                }
            }
        }
    }

    if (lane < KNN) {
#pragma unroll
        for (int u = 0; u < QW; u++)
            out_idx[((size_t)b * NPTS + qbase + u) * KNN + lane] = idx[u];
    }
}

// ---------------- attention over K=8 neighbors (float4, writes bf16 hi/lo agg) ---
__global__ __launch_bounds__(256) void attn_kernel(const float* __restrict__ coords,
                                                   const float* __restrict__ logg)
{
    const int gq   = blockIdx.x * 8 + (threadIdx.x >> 5);
    const int b    = gq >> 13;
    const int q    = gq & (NPTS - 1);
    const int lane = threadIdx.x & 31;
    const float lg = *logg;
    const float inv_sqrt_c = 0.08838834764831845f;   // 1/sqrt(128)

    float4 qv = *(const float4*)(g_q + (size_t)gq * CH + lane * 4);

    const float* cb = coords + (size_t)b * NPTS * 3;
    const float qx = cb[q * 3 + 0], qy = cb[q * 3 + 1], qz = cb[q * 3 + 2];

    int nb[KNN];
#pragma unroll
    for (int t = 0; t < KNN; t++) nb[t] = g_idx[(size_t)gq * KNN + t];

    float sc[KNN];
#pragma unroll
    for (int t = 0; t < KNN; t++) {
        float4 kv = *(const float4*)(g_k + ((size_t)b * NPTS + nb[t]) * CH + lane * 4);
        float d = qv.x * kv.x;
        d = fmaf(qv.y, kv.y, d);
        d = fmaf(qv.z, kv.z, d);
        d = fmaf(qv.w, kv.w, d);
#pragma unroll
        for (int off = 16; off; off >>= 1) d += __shfl_xor_sync(0xffffffffu, d, off);
        float dx = qx - cb[nb[t] * 3 + 0];
        float dy = qy - cb[nb[t] * 3 + 1];
        float dz = qz - cb[nb[t] * 3 + 2];
        float d2 = fmaf(dz, dz, fmaf(dy, dy, dx * dx));
        float dist = (d2 > 0.f) ? sqrtf(d2) : 0.f;     // _safe_norm
        float gw = expf(lg * dist);
        sc[t] = d * inv_sqrt_c * gw;
    }
    float m = sc[0];
#pragma unroll
    for (int t = 1; t < KNN; t++) m = fmaxf(m, sc[t]);
    float ssum = 0.f;
#pragma unroll
    for (int t = 0; t < KNN; t++) { sc[t] = expf(sc[t] - m); ssum += sc[t]; }
    float inv = 1.f / ssum;

    float4 acc = make_float4(0.f, 0.f, 0.f, 0.f);
#pragma unroll
    for (int t = 0; t < KNN; t++) {
        float4 vv = *(const float4*)(g_v + ((size_t)b * NPTS + nb[t]) * CH + lane * 4);
        float wt = sc[t] * inv;
        acc.x = fmaf(wt, vv.x, acc.x);
        acc.y = fmaf(wt, vv.y, acc.y);
        acc.z = fmaf(wt, vv.z, acc.z);
        acc.w = fmaf(wt, vv.w, acc.w);
    }
    // write agg in bf16 hi/lo X-pattern: channels (4l,4l+1) and (4l+2,4l+3)
    unsigned pa = pack_hilo(acc.x), pb = pack_hilo(acc.y);
    unsigned pc = pack_hilo(acc.z), pd = pack_hilo(acc.w);
    g_agg2[(size_t)gq * 64 + lane * 2 + 0] = make_uint4(pa, pa, pb, pb);
    g_agg2[(size_t)gq * 64 + lane * 2 + 1] = make_uint4(pc, pc, pd, pd);
}

// ---------------- launch ----------------
extern "C" void kernel_launch(void* const* d_in, const int* in_sizes, int n_in,
                              void* d_out, int out_size)
{
    const float* feats  = (const float*)d_in[0];
    const float* coords = (const float*)d_in[1];
    const float* Wq     = (const float*)d_in[2];
    const float* Wk     = (const float*)d_in[3];
    const float* Wv     = (const float*)d_in[4];
    const float* Wo     = (const float*)d_in[5];
    const float* logg   = (const float*)d_in[6];
    float* out = (float*)d_out;

    int* idx_ptr = nullptr;
    cudaGetSymbolAddress((void**)&idx_ptr, g_idx);

    // KNN top-8 per query (32 queries/CTA)
    knn_kernel<<<dim3(NPTS / 32, BATCH), 256>>>(coords, idx_ptr);

    // q,k,v projections on tensor cores (feats + W split inline)
    qkv_mma_kernel<<<dim3(MTOT / 128, 3), 256>>>(feats, Wq, Wk, Wv);

    // neighbor attention -> g_agg2 (bf16 hi/lo)
    attn_kernel<<<MTOT / 8, 256>>>(coords, logg);

    // output projection (Wo split inline)
    out_mma_kernel<<<MTOT / 128, 256>>>(Wo, out);
}

// round 9
// speedup vs baseline: 1.7164x; 1.1611x over previous
#include <cuda_runtime.h>
#include <cuda_bf16.h>
#include <math.h>

#define BATCH 2
#define NPTS  8192
#define CH    128
#define KNN   8
#define MTOT  (BATCH * NPTS)

// ---------------- scratch (no allocations allowed) ----------------
__device__ float g_q[MTOT * CH];
__device__ float g_k[MTOT * CH];
__device__ float g_v[MTOT * CH];
__device__ int   g_idx[MTOT * KNN];
__device__ uint4 g_agg2[MTOT * 64];    // agg split, X-pattern (hi,lo,hi,lo)

// ---------------- fp32 -> (hi,lo) bf16 split helpers ----------------
__device__ __forceinline__ void split_bf16(float x, unsigned short& h, unsigned short& l) {
    __nv_bfloat16 hb = __float2bfloat16(x);
    float hf = __bfloat162float(hb);
    __nv_bfloat16 lb = __float2bfloat16(x - hf);
    h = __bfloat16_as_ushort(hb);
    l = __bfloat16_as_ushort(lb);
}
__device__ __forceinline__ unsigned pack_hilo(float x) {   // X-pattern word (hi,lo)
    unsigned short h, l; split_bf16(x, h, l);
    return ((unsigned)l << 16) | (unsigned)h;
}
__device__ __forceinline__ void pack_w(float x, unsigned& p0, unsigned& p1) { // (hi,hi),(lo,lo)
    unsigned short h, l; split_bf16(x, h, l);
    p0 = ((unsigned)h << 16) | h;
    p1 = ((unsigned)l << 16) | l;
}

// ---------------- tensor-core GEMM:  Y = X @ W^T via bf16 split-K ----------------
// 64x128 CTA tile, 256 threads = 8 warps (2x4), warp tile 32x32, mma.m16n8k16.
// W fp32 split inline; X fp32 (SPLIT_X) or pre-split uint4 X-pattern.
// smem rows padded to 144B -> conflict-free LDS.32 fragment loads.
template <bool SPLIT_X>
__device__ __forceinline__ void mma_gemm_tile(const void* __restrict__ Xv,
                                              const float* __restrict__ Wf,
                                              float* __restrict__ Y, int m0)
{
    __shared__ __align__(16) unsigned char xs[64 * 144];
    __shared__ __align__(16) unsigned char ws[128 * 144];
    const int tid  = threadIdx.x;
    const int lane = tid & 31;
    const int warp = tid >> 5;
    const int wm   = warp >> 2;       // 0..1 -> rows wm*32
    const int wn   = warp & 3;        // 0..3 -> cols wn*32
    const int g    = lane >> 2;       // 0..7
    const int c4   = lane & 3;        // 0..3

    float acc[2][4][4];
#pragma unroll
    for (int i = 0; i < 2; i++)
#pragma unroll
        for (int t = 0; t < 4; t++)
#pragma unroll
            for (int r = 0; r < 4; r++) acc[i][t][r] = 0.f;

    for (int kc = 0; kc < 8; kc++) {        // K' = 512 in chunks of 64
        __syncthreads();
        // stage X: 64 rows x 8 uint4 = 512 slots, 2 per thread
#pragma unroll
        for (int i = 0; i < 2; i++) {
            int s  = tid + i * 256;
            int r  = s >> 3;
            int f4 = s & 7;
            if (SPLIT_X) {
                const float* X = (const float*)Xv;
                float2 xv = *(const float2*)(X + (size_t)(m0 + r) * CH + kc * 16 + f4 * 2);
                unsigned p0 = pack_hilo(xv.x), p1 = pack_hilo(xv.y);
                *(uint4*)(xs + r * 144 + f4 * 16) = make_uint4(p0, p0, p1, p1);
            } else {
                const uint4* X2 = (const uint4*)Xv;
                *(uint4*)(xs + r * 144 + f4 * 16) = X2[(size_t)(m0 + r) * 64 + kc * 8 + f4];
            }
        }
        // stage W: 128 rows x 8 uint4 = 1024 slots, 4 per thread
#pragma unroll
        for (int i = 0; i < 4; i++) {
            int s  = tid + i * 256;
            int r  = s >> 3;
            int f4 = s & 7;
            float2 wv = *(const float2*)(Wf + (size_t)r * CH + kc * 16 + f4 * 2);
            unsigned a0, a1, b0, b1;
            pack_w(wv.x, a0, a1);
            pack_w(wv.y, b0, b1);
            *(uint4*)(ws + r * 144 + f4 * 16) = make_uint4(a0, a1, b0, b1);
        }
        __syncthreads();
#pragma unroll
        for (int ks = 0; ks < 4; ks++) {    // 4 x k16 steps
            unsigned a[2][4], b[4][2];
#pragma unroll
            for (int i = 0; i < 2; i++)
#pragma unroll
                for (int j = 0; j < 4; j++) {
                    int row = wm * 32 + i * 16 + g + 8 * (j & 1);
                    int off = ks * 32 + (j >> 1) * 16 + c4 * 4;
                    a[i][j] = *(const unsigned*)(xs + row * 144 + off);
                }
#pragma unroll
            for (int t = 0; t < 4; t++)
#pragma unroll
                for (int r = 0; r < 2; r++) {
                    int n   = wn * 32 + t * 8 + g;
                    int off = ks * 32 + r * 16 + c4 * 4;
                    b[t][r] = *(const unsigned*)(ws + n * 144 + off);
                }
#pragma unroll
            for (int i = 0; i < 2; i++)
#pragma unroll
                for (int t = 0; t < 4; t++)
                    asm volatile(
                        "mma.sync.aligned.m16n8k16.row.col.f32.bf16.bf16.f32 "
                        "{%0,%1,%2,%3}, {%4,%5,%6,%7}, {%8,%9}, {%0,%1,%2,%3};"
                        : "+f"(acc[i][t][0]), "+f"(acc[i][t][1]),
                          "+f"(acc[i][t][2]), "+f"(acc[i][t][3])
                        : "r"(a[i][0]), "r"(a[i][1]), "r"(a[i][2]), "r"(a[i][3]),
                          "r"(b[t][0]), "r"(b[t][1]));
        }
    }
#pragma unroll
    for (int i = 0; i < 2; i++)
#pragma unroll
        for (int t = 0; t < 4; t++) {
            int row = m0 + wm * 32 + i * 16 + g;
            int col = wn * 32 + t * 8 + 2 * c4;
            *(float2*)(Y + (size_t)row * CH + col)       = make_float2(acc[i][t][0], acc[i][t][1]);
            *(float2*)(Y + (size_t)(row + 8) * CH + col) = make_float2(acc[i][t][2], acc[i][t][3]);
        }
}

__global__ __launch_bounds__(256) void qkv_mma_kernel(const float* __restrict__ feats,
                                                      const float* __restrict__ Wq,
                                                      const float* __restrict__ Wk,
                                                      const float* __restrict__ Wv)
{
    int w = blockIdx.y;
    const float* W = (w == 0) ? Wq : (w == 1) ? Wk : Wv;
    float* Y = (w == 0) ? g_q : (w == 1) ? g_k : g_v;
    mma_gemm_tile<true>(feats, W, Y, blockIdx.x * 64);
}

__global__ __launch_bounds__(256) void out_mma_kernel(const float* __restrict__ Wo,
                                                      float* __restrict__ out)
{
    mma_gemm_tile<false>(g_agg2, Wo, out, blockIdx.x * 64);
}

// ---------------- KNN: warp top-8; R6 scalar fast path + R4 insert walk ---------
// e-space ordering: e = csq - 2*dot (query-constant shift of d2; same top-k set).
// Fast path: 4 candidates/lane (float4 LDS from SoA), 3 FMA each, one __any
// per 128-candidate group per query. On fire: ballot-walk insert (R4-proven).
#define QW  4
#define CCH 2048

__device__ __forceinline__ void try_insert4(float d2, int base,
                                            float& val, int& idx, float& thr)
{
    // candidate index for lane 'src' is base + 4*src
    const unsigned full = 0xffffffffu;
    unsigned m = __ballot_sync(full, d2 < thr);
    const int lane = threadIdx.x & 31;
    while (m) {
        int src = __ffs(m) - 1;
        m &= m - 1;
        float dn = __shfl_sync(full, d2, src);
        if (dn < thr) {                         // warp-uniform
            int   in = base + (src << 2);
            float pv = __shfl_up_sync(full, val, 1);
            int   pi = __shfl_up_sync(full, idx, 1);
            unsigned le = __ballot_sync(full, val <= dn);
            int pos = __popc(le & 0xff);
            if (lane == pos)                  { val = dn; idx = in; }
            else if (lane > pos && lane < 8)  { val = pv; idx = pi; }
            thr = __shfl_sync(full, val, 7);
        }
    }
}

__global__ __launch_bounds__(256, 3) void knn_kernel(const float* __restrict__ coords,
                                                     int* __restrict__ out_idx)
{
    __shared__ float sx[CCH], sy[CCH], sz[CCH], ss[CCH];
    const unsigned full = 0xffffffffu;
    const int b     = blockIdx.y;
    const int warp  = threadIdx.x >> 5;
    const int lane  = threadIdx.x & 31;
    const int qbase = blockIdx.x * (8 * QW) + warp * QW;
    const float* cb = coords + (size_t)b * NPTS * 3;

    float m2x[QW], m2y[QW], m2z[QW];
#pragma unroll
    for (int u = 0; u < QW; u++) {
        m2x[u] = -2.f * cb[(qbase + u) * 3 + 0];
        m2y[u] = -2.f * cb[(qbase + u) * 3 + 1];
        m2z[u] = -2.f * cb[(qbase + u) * 3 + 2];
    }

    float val[QW], thr[QW];
    int idx[QW];
#pragma unroll
    for (int u = 0; u < QW; u++) { val[u] = 3.0e38f; thr[u] = 3.0e38f; idx[u] = -1; }

    for (int c0 = 0; c0 < NPTS; c0 += CCH) {
        __syncthreads();
        for (int t = threadIdx.x; t < CCH; t += 256) {
            float x = cb[(c0 + t) * 3 + 0];
            float y = cb[(c0 + t) * 3 + 1];
            float z = cb[(c0 + t) * 3 + 2];
            sx[t] = x; sy[t] = y; sz[t] = z;
            ss[t] = fmaf(z, z, fmaf(y, y, x * x));
        }
        __syncthreads();

        for (int j0 = 0; j0 < CCH; j0 += 128) {
            int base = j0 + lane * 4;
            float4 cx = *(const float4*)&sx[base];
            float4 cy = *(const float4*)&sy[base];
            float4 cz = *(const float4*)&sz[base];
            float4 cs = *(const float4*)&ss[base];
            int jb = c0 + j0;                        // warp-uniform
#pragma unroll
            for (int u = 0; u < QW; u++) {
                float e0 = fmaf(m2z[u], cz.x, fmaf(m2y[u], cy.x, fmaf(m2x[u], cx.x, cs.x)));
                float e1 = fmaf(m2z[u], cz.y, fmaf(m2y[u], cy.y, fmaf(m2x[u], cx.y, cs.y)));
                float e2 = fmaf(m2z[u], cz.z, fmaf(m2y[u], cy.z, fmaf(m2x[u], cx.z, cs.z)));
                float e3 = fmaf(m2z[u], cz.w, fmaf(m2y[u], cy.w, fmaf(m2x[u], cx.w, cs.w)));
                float lm = fminf(fminf(e0, e1), fminf(e2, e3));
                if (__any_sync(full, lm < thr[u])) {
                    try_insert4(e0, jb + 0, val[u], idx[u], thr[u]);
                    try_insert4(e1, jb + 1, val[u], idx[u], thr[u]);
                    try_insert4(e2, jb + 2, val[u], idx[u], thr[u]);
                    try_insert4(e3, jb + 3, val[u], idx[u], thr[u]);
                }
            }
        }
    }

    if (lane < KNN) {
#pragma unroll
        for (int u = 0; u < QW; u++)
            out_idx[((size_t)b * NPTS + qbase + u) * KNN + lane] = idx[u];
    }
}

// ---------------- attention over K=8 neighbors (float4, writes bf16 hi/lo agg) ---
__global__ __launch_bounds__(256) void attn_kernel(const float* __restrict__ coords,
                                                   const float* __restrict__ logg)
{
    const int gq   = blockIdx.x * 8 + (threadIdx.x >> 5);
    const int b    = gq >> 13;
    const int q    = gq & (NPTS - 1);
    const int lane = threadIdx.x & 31;
    const float lg = *logg;
    const float inv_sqrt_c = 0.08838834764831845f;   // 1/sqrt(128)

    float4 qv = *(const float4*)(g_q + (size_t)gq * CH + lane * 4);

    const float* cb = coords + (size_t)b * NPTS * 3;
    const float qx = cb[q * 3 + 0], qy = cb[q * 3 + 1], qz = cb[q * 3 + 2];

    int nb[KNN];
#pragma unroll
    for (int t = 0; t < KNN; t++) nb[t] = g_idx[(size_t)gq * KNN + t];

    float sc[KNN];
#pragma unroll
    for (int t = 0; t < KNN; t++) {
        float4 kv = *(const float4*)(g_k + ((size_t)b * NPTS + nb[t]) * CH + lane * 4);
        float d = qv.x * kv.x;
        d = fmaf(qv.y, kv.y, d);
        d = fmaf(qv.z, kv.z, d);
        d = fmaf(qv.w, kv.w, d);
#pragma unroll
        for (int off = 16; off; off >>= 1) d += __shfl_xor_sync(0xffffffffu, d, off);
        float dx = qx - cb[nb[t] * 3 + 0];
        float dy = qy - cb[nb[t] * 3 + 1];
        float dz = qz - cb[nb[t] * 3 + 2];
        float d2 = fmaf(dz, dz, fmaf(dy, dy, dx * dx));
        float dist = (d2 > 0.f) ? sqrtf(d2) : 0.f;     // _safe_norm
        float gw = expf(lg * dist);
        sc[t] = d * inv_sqrt_c * gw;
    }
    float m = sc[0];
#pragma unroll
    for (int t = 1; t < KNN; t++) m = fmaxf(m, sc[t]);
    float ssum = 0.f;
#pragma unroll
    for (int t = 0; t < KNN; t++) { sc[t] = expf(sc[t] - m); ssum += sc[t]; }
    float inv = 1.f / ssum;

    float4 acc = make_float4(0.f, 0.f, 0.f, 0.f);
#pragma unroll
    for (int t = 0; t < KNN; t++) {
        float4 vv = *(const float4*)(g_v + ((size_t)b * NPTS + nb[t]) * CH + lane * 4);
        float wt = sc[t] * inv;
        acc.x = fmaf(wt, vv.x, acc.x);
        acc.y = fmaf(wt, vv.y, acc.y);
        acc.z = fmaf(wt, vv.z, acc.z);
        acc.w = fmaf(wt, vv.w, acc.w);
    }
    // write agg in bf16 hi/lo X-pattern: channels (4l,4l+1) and (4l+2,4l+3)
    unsigned pa = pack_hilo(acc.x), pb = pack_hilo(acc.y);
    unsigned pc = pack_hilo(acc.z), pd = pack_hilo(acc.w);
    g_agg2[(size_t)gq * 64 + lane * 2 + 0] = make_uint4(pa, pa, pb, pb);
    g_agg2[(size_t)gq * 64 + lane * 2 + 1] = make_uint4(pc, pc, pd, pd);
}

// ---------------- launch ----------------
extern "C" void kernel_launch(void* const* d_in, const int* in_sizes, int n_in,
                              void* d_out, int out_size)
{
    const float* feats  = (const float*)d_in[0];
    const float* coords = (const float*)d_in[1];
    const float* Wq     = (const float*)d_in[2];
    const float* Wk     = (const float*)d_in[3];
    const float* Wv     = (const float*)d_in[4];
    const float* Wo     = (const float*)d_in[5];
    const float* logg   = (const float*)d_in[6];
    float* out = (float*)d_out;

    int* idx_ptr = nullptr;
    cudaGetSymbolAddress((void**)&idx_ptr, g_idx);

    // KNN top-8 per query (32 queries/CTA)
    knn_kernel<<<dim3(NPTS / 32, BATCH), 256>>>(coords, idx_ptr);

    // q,k,v projections on tensor cores (feats + W split inline)
    qkv_mma_kernel<<<dim3(MTOT / 64, 3), 256>>>(feats, Wq, Wk, Wv);

    // neighbor attention -> g_agg2 (bf16 hi/lo)
    attn_kernel<<<MTOT / 8, 256>>>(coords, logg);

    // output projection (Wo split inline)
    out_mma_kernel<<<MTOT / 64, 256>>>(Wo, out);
}